// round 14
// baseline (speedup 1.0000x reference)
#include <cuda_runtime.h>
#include <cuda_fp16.h>
#include <cstdint>
#include <cstddef>
#include <math.h>

// ---------------- problem constants ----------------
#define BTOK  16384
#define IND   512
#define HIDD  2048
#define NEXP  8
#define NTOP  4

// ---------------- tiling ----------------
#define TM      128               // tokens per block
#define TN      128               // hidden cols per block
#define KBPST   4                 // K=16 blocks per stage => K=64
#define NST     3
#define NKCH    8                 // mainloop iterations (512/64)
#define HTILES  (HIDD / TN)       // 16
#define MTILES  (BTOK / TM)       // 128 (worst case)
#define NTHR    256

// packed-fragment stage sizes (fp16)
#define A_BYTES 16384
#define B_BYTES 16384
#define STAGE_BYTES (A_BYTES + B_BYTES)       // 32768
#define SMEM_TOTAL  (NST * STAGE_BYTES)       // 98304  (2 CTAs/SM)

#define A_TILE_BYTES  16384    // one 16-row m-tile: 32 kb x 32 lanes x 16B
#define B_TILE_BYTES  8192     // one 8-col h-tile: 32 kb x 32 lanes x 8B

// k_prep roles
#define TRN_BLOCKS 4096        // 16 hc x 32 kb x 8 e
#define GATE_BLOCKS (BTOK / 8) // 2048

// ---------------- device scratch ----------------
// A packed (half2 as uint): [e][slot/16][kb][lane][4]
//   word w: row = grp + 8*(w&1); k = kb*16 + 8*(w>>1) + 2*qid + {0,1}
__device__ __align__(1024) uint32_t g_xcu[(size_t)NEXP * BTOK * IND / 2];
// B packed (half2 as uint): [e][h/8][kb][lane][2]
__device__ __align__(1024) uint32_t g_w1u[(size_t)NEXP * HIDD * IND / 2];
// single fp16 row-major copy of x (half2 words): [tok][256]
__device__ __align__(1024) uint32_t g_xh[(size_t)BTOK * 256];
__device__ int   g_tok[(size_t)NEXP * BTOK];   // slot -> token
__device__ int   g_cnt[NEXP];       // zero-init; re-zeroed by k_combine each call
__device__ int   g_sel[BTOK * NTOP];
__device__ int   g_slot[BTOK * NTOP];
__device__ float g_g4[BTOK * NTOP];
__device__ float g_part[(size_t)NEXP * BTOK * HTILES];

// ---------------- helpers ----------------
__device__ __forceinline__ void cp_async16(uint32_t saddr, const void* gaddr) {
    asm volatile("cp.async.cg.shared.global [%0], [%1], 16;" :: "r"(saddr), "l"(gaddr) : "memory");
}
__device__ __forceinline__ uint32_t smem_u32(const void* p) {
    uint32_t a;
    asm("{ .reg .u64 t; cvta.to.shared.u64 t, %1; cvt.u32.u64 %0, t; }" : "=r"(a) : "l"(p));
    return a;
}
__device__ __forceinline__ void mma_f16(float* c, const uint32_t* a, const uint32_t* b) {
    asm volatile(
        "mma.sync.aligned.m16n8k16.row.col.f32.f16.f16.f32 "
        "{%0,%1,%2,%3}, {%4,%5,%6,%7}, {%8,%9}, {%0,%1,%2,%3};"
        : "+f"(c[0]), "+f"(c[1]), "+f"(c[2]), "+f"(c[3])
        : "r"(a[0]), "r"(a[1]), "r"(a[2]), "r"(a[3]), "r"(b[0]), "r"(b[1]));
}

// ============================================================
// kernel 1 (fused): blocks [0,4096) transpose W1; rest do gating
// ============================================================
__global__ void k_prep(const float* __restrict__ W1,
                       const float* __restrict__ x,
                       const float* __restrict__ wg) {
    __shared__ float tile[16][129];          // transpose role
    __shared__ int   s_cnt[NEXP];            // gate role
    __shared__ int   s_base[NEXP];

    const int tid = threadIdx.x;

    if (blockIdx.x < TRN_BLOCKS) {
        // ------- transpose role: W1 -> packed fp16 B-fragment layout -------
        int hc = blockIdx.x & 15;            // 128-h chunk
        int kb = (blockIdx.x >> 4) & 31;     // K=16 block
        int e  = blockIdx.x >> 9;

        #pragma unroll
        for (int it = 0; it < 8; ++it) {
            int idx = tid + it * 256;
            int kr = idx >> 7, hf = idx & 127;
            tile[kr][hf] = W1[((size_t)e * IND + kb * 16 + kr) * HIDD + hc * 128 + hf];
        }
        __syncthreads();

        size_t base2 = (size_t)e * (HIDD * IND / 2);
        #pragma unroll
        for (int it = 0; it < 4; ++it) {
            int w    = tid + it * 256;
            int h8l  = w >> 6;
            int rem  = w & 63;
            int lane = rem >> 1, rj = rem & 1;
            int grp  = lane >> 2, qid = lane & 3;
            int hl   = h8l * 8 + grp;
            int k0   = rj * 8 + qid * 2;
            __half2 v = __floats2half2_rn(tile[k0][hl], tile[k0 + 1][hl]);
            g_w1u[base2 + (size_t)(hc * 16 + h8l) * 2048 + (kb * 32 + lane) * 2 + rj]
                = *(uint32_t*)&v;
        }
        return;
    }

    // ------- gate role: 8 tokens per block, batched atomics -------
    int wid  = tid >> 5;
    int lane = tid & 31;
    int tok  = (blockIdx.x - TRN_BLOCKS) * 8 + wid;
    const float* xr = x + (size_t)tok * IND;

    if (tid < NEXP) s_cnt[tid] = 0;

    float acc[NEXP];
    #pragma unroll
    for (int e = 0; e < NEXP; ++e) acc[e] = 0.f;
    for (int i = lane; i < IND; i += 32) {
        float xv = xr[i];
        #pragma unroll
        for (int e = 0; e < NEXP; ++e) acc[e] = fmaf(xv, wg[i * NEXP + e], acc[e]);
    }
    #pragma unroll
    for (int off = 16; off > 0; off >>= 1) {
        #pragma unroll
        for (int e = 0; e < NEXP; ++e)
            acc[e] += __shfl_xor_sync(0xFFFFFFFFu, acc[e], off);
    }

    // top-4: strict '>' keeps lowest index on ties (matches jax.lax.top_k)
    int   sel[NTOP];
    float val[NTOP];
    bool  used[NEXP];
    #pragma unroll
    for (int e = 0; e < NEXP; ++e) used[e] = false;
    #pragma unroll
    for (int k = 0; k < NTOP; ++k) {
        float best = -1e30f; int be = 0;
        #pragma unroll
        for (int e = 0; e < NEXP; ++e)
            if (!used[e] && acc[e] > best) { best = acc[e]; be = e; }
        used[be] = true; sel[k] = be; val[k] = best;
    }
    float s = 0.f, gt[NTOP];
    #pragma unroll
    for (int k = 0; k < NTOP; ++k) { gt[k] = expf(val[k] - val[0]); s += gt[k]; }
    float inv = 1.f / s;
    #pragma unroll
    for (int k = 0; k < NTOP; ++k) gt[k] *= inv;

    // batched slot assignment: smem-local offsets, then <=8 global atomics
    __syncthreads();
    int loc[NTOP];
    if (lane == 0) {
        #pragma unroll
        for (int k = 0; k < NTOP; ++k) loc[k] = atomicAdd(&s_cnt[sel[k]], 1);
    }
    __syncthreads();
    if (tid < NEXP && s_cnt[tid] > 0) s_base[tid] = atomicAdd(&g_cnt[tid], s_cnt[tid]);
    __syncthreads();

    int slot[NTOP];
    #pragma unroll
    for (int k = 0; k < NTOP; ++k) {
        int l = __shfl_sync(0xFFFFFFFFu, loc[k], 0);
        slot[k] = s_base[sel[k]] + l;
    }

    if (lane < NTOP) {
        g_sel[tok * NTOP + lane]  = sel[lane];
        g_slot[tok * NTOP + lane] = slot[lane];
        g_g4[tok * NTOP + lane]   = gt[lane];
        g_tok[(size_t)sel[lane] * BTOK + slot[lane]] = tok;
    }

    // single coalesced fp16 row write (half2 word p = lane + it*32)
    #pragma unroll
    for (int it = 0; it < 8; ++it) {
        int p = lane + it * 32;
        __half2 v = __floats2half2_rn(xr[2 * p], xr[2 * p + 1]);
        g_xh[(size_t)tok * 256 + p] = *(uint32_t*)&v;
    }
}

// ============================================================
// kernel 1b: repack rows -> packed-fragment A tiles (coalesced both sides)
// grid (1024 tiles, 8 experts), 256 threads
// ============================================================
#define SROWW 260   // smem row stride in half2 words (256 + 4 pad; %4==0 for uint4)
__global__ void k_repack() {
    __shared__ uint32_t srow[16 * SROWW];
    int e    = blockIdx.y;
    int tile = blockIdx.x;
    int cnt  = g_cnt[e];
    int s0   = tile * 16;
    if (s0 >= cnt) return;
    int tid = threadIdx.x;

    // gather 16 rows (1KB each) into smem
    #pragma unroll
    for (int it = 0; it < 4; ++it) {
        int c = tid + it * 256;          // 0..1023
        int r = c & 15, q = c >> 4;      // q = uint4 chunk 0..63
        int slot = s0 + r;
        if (slot < cnt) {
            int tok = g_tok[(size_t)e * BTOK + slot];
            uint4 v = *(const uint4*)(g_xh + (size_t)tok * 256 + q * 4);
            *(uint4*)&srow[r * SROWW + q * 4] = v;
        }
    }
    __syncthreads();

    // emit packed tile: out uint4 chunk c = (kb, lane); words per layout formula
    // read banks: grp*4 + kb*8 + qid (mod 32) distinct across a warp -> conflict-free
    size_t obase = (size_t)e * (BTOK * IND / 2) + (size_t)tile * 4096;
    #pragma unroll
    for (int it = 0; it < 4; ++it) {
        int c   = tid + it * 256;        // 0..1023
        int kb  = c >> 5, lo = c & 31;
        int grp = lo >> 2, qid = lo & 3;
        int k0w = kb * 8 + qid;          // half2 word, khalf 0
        int k1w = k0w + 4;               // khalf 1
        uint4 ov;
        ov.x = srow[grp * SROWW + k0w];
        ov.y = srow[(grp + 8) * SROWW + k0w];
        ov.z = srow[grp * SROWW + k1w];
        ov.w = srow[(grp + 8) * SROWW + k1w];
        *(uint4*)(g_xcu + obase + (size_t)c * 4) = ov;
    }
}

// ============================================================
// kernel 2: expert GEMM fp16 m16n8k16 (fc1 + relu + fc2-partial)
// grid (HTILES, MTILES, NEXP), 256 threads, 2 CTAs/SM
// ============================================================
__device__ __forceinline__ void load_stage(uint32_t sb, int s, int kt, int tid,
                                           const char* Ag, const char* Bg) {
    uint32_t abase = sb + (uint32_t)s * STAGE_BYTES;
    uint32_t bbase = abase + A_BYTES;
    #pragma unroll
    for (int it = 0; it < 4; ++it) {
        int c    = tid + it * NTHR;
        int tile = c >> 7, rem = c & 127;
        cp_async16(abase + (uint32_t)c * 16,
                   Ag + (size_t)tile * A_TILE_BYTES + kt * 2048 + rem * 16);
    }
    #pragma unroll
    for (int it = 0; it < 4; ++it) {
        int c    = tid + it * NTHR;
        int tile = c >> 6, rem = c & 63;
        cp_async16(bbase + (uint32_t)c * 16,
                   Bg + (size_t)tile * B_TILE_BYTES + kt * 1024 + rem * 16);
    }
    asm volatile("cp.async.commit_group;" ::: "memory");
}

__global__ void __launch_bounds__(NTHR, 2)
k_expert(const float* __restrict__ W2, const float* __restrict__ b1) {
    extern __shared__ char smem[];
    const int e     = blockIdx.z;
    const int mtile = blockIdx.y;
    const int ht    = blockIdx.x;
    const int cnt   = g_cnt[e];
    const int m0    = mtile * TM;
    if (m0 >= cnt) return;

    const int tid  = threadIdx.x;
    const int wid  = tid >> 5;
    const int lane = tid & 31;
    const int wm   = wid >> 2;       // 0..1 : rows wm*64
    const int wn   = wid & 3;        // 0..3 : cols wn*32
    const int grp  = lane >> 2;
    const int qid  = lane & 3;

    // epilogue weight prefetch (hides gmem latency behind the mainloop)
    float w2r = 0.f, b1r = 0.f;
    if (tid < TN) {
        w2r = W2[(size_t)e * HIDD + ht * TN + tid];
        b1r = b1[(size_t)e * HIDD + ht * TN + tid];
    }

    uint32_t sb = smem_u32(smem);
    const char* Ag = (const char*)g_xcu + (size_t)e * (BTOK * IND * 2)
                   + (size_t)(m0 >> 4) * A_TILE_BYTES;
    const char* Bg = (const char*)g_w1u + (size_t)e * (HIDD * IND * 2)
                   + (size_t)(ht * (TN / 8)) * B_TILE_BYTES;

    float acc[4][4][4];
    #pragma unroll
    for (int mt = 0; mt < 4; ++mt)
        #pragma unroll
        for (int nt = 0; nt < 4; ++nt)
            #pragma unroll
            for (int r = 0; r < 4; ++r) acc[mt][nt][r] = 0.f;

    load_stage(sb, 0, 0, tid, Ag, Bg);
    load_stage(sb, 1, 1, tid, Ag, Bg);

    for (int kt = 0; kt < NKCH; ++kt) {
        asm volatile("cp.async.wait_group 1;" ::: "memory");
        __syncthreads();
        int kn = kt + 2;
        if (kn < NKCH) load_stage(sb, kn % NST, kn, tid, Ag, Bg);
        else asm volatile("cp.async.commit_group;" ::: "memory");

        int cs = kt % NST;
        const uint4* sA = (const uint4*)(smem + (size_t)cs * STAGE_BYTES);
        const uint2* sB = (const uint2*)(smem + (size_t)cs * STAGE_BYTES + A_BYTES);

        #pragma unroll
        for (int ks = 0; ks < KBPST; ++ks) {             // 4 K=16 steps
            uint4 af[4];
            uint2 bf[4];
            #pragma unroll
            for (int mt = 0; mt < 4; ++mt)
                af[mt] = sA[((wm * 4 + mt) * 4 + ks) * 32 + lane];
            #pragma unroll
            for (int nt = 0; nt < 4; ++nt)
                bf[nt] = sB[((wn * 4 + nt) * 4 + ks) * 32 + lane];
            #pragma unroll
            for (int mt = 0; mt < 4; ++mt)
                #pragma unroll
                for (int nt = 0; nt < 4; ++nt)
                    mma_f16(acc[mt][nt], (const uint32_t*)&af[mt], (const uint32_t*)&bf[nt]);
        }
    }
    __syncthreads();

    // ---- fused epilogue: relu(h + b1) . W2 over this 128-col tile ----
    float* red = (float*)smem;                 // [TM][4]
    float* w2s = (float*)(smem + TM * 4 * 4);  // [TN]
    float* b1s = w2s + TN;                     // [TN]
    if (tid < TN) {
        w2s[tid] = w2r;
        b1s[tid] = b1r;
    }
    __syncthreads();

    #pragma unroll
    for (int mt = 0; mt < 4; ++mt) {
        #pragma unroll
        for (int rr = 0; rr < 2; ++rr) {
            int row = wm * 64 + mt * 16 + grp + rr * 8;
            float v = 0.f;
            #pragma unroll
            for (int nt = 0; nt < 4; ++nt) {
                int col = wn * 32 + nt * 8 + qid * 2;
                float h0 = fmaxf(acc[mt][nt][rr * 2 + 0] + b1s[col], 0.f);
                float h1 = fmaxf(acc[mt][nt][rr * 2 + 1] + b1s[col + 1], 0.f);
                v = fmaf(h0, w2s[col], v);
                v = fmaf(h1, w2s[col + 1], v);
            }
            v += __shfl_down_sync(0xFFFFFFFFu, v, 2);
            v += __shfl_down_sync(0xFFFFFFFFu, v, 1);
            if (qid == 0) red[row * 4 + wn] = v;
        }
    }
    __syncthreads();

    if (tid < TM) {
        float p = red[tid * 4 + 0] + red[tid * 4 + 1] + red[tid * 4 + 2] + red[tid * 4 + 3];
        g_part[((size_t)e * BTOK + m0 + tid) * HTILES + ht] = p;
    }
}

// ============================================================
// kernel 3: weighted combine + counter reset for next call
// ============================================================
__global__ void k_combine(float* __restrict__ out, const float* __restrict__ b2) {
    int t = blockIdx.x * blockDim.x + threadIdx.x;
    if (blockIdx.x == 0 && threadIdx.x < NEXP) g_cnt[threadIdx.x] = 0;
    if (t >= BTOK) return;
    float y = 0.f;
    #pragma unroll
    for (int k = 0; k < NTOP; ++k) {
        int   e = g_sel[t * NTOP + k];
        int   s = g_slot[t * NTOP + k];
        float g = g_g4[t * NTOP + k];
        float p = b2[e];
        const float* pp = &g_part[((size_t)e * BTOK + s) * HTILES];
        #pragma unroll
        for (int h = 0; h < HTILES; ++h) p += pp[h];
        y = fmaf(g, p, y);
    }
    out[t] = y;
}

// ============================================================
// launch
// ============================================================
extern "C" void kernel_launch(void* const* d_in, const int* in_sizes, int n_in,
                              void* d_out, int out_size) {
    const float* x  = (const float*)d_in[0];   // [16384, 512]
    const float* wg = (const float*)d_in[1];   // [512, 8]
    const float* W1 = (const float*)d_in[2];   // [8, 512, 2048]
    const float* b1 = (const float*)d_in[3];   // [8, 2048]
    const float* W2 = (const float*)d_in[4];   // [8, 2048, 1]
    const float* b2 = (const float*)d_in[5];   // [8, 1]
    float* out = (float*)d_out;                // [16384, 1]

    cudaFuncSetAttribute(k_expert, cudaFuncAttributeMaxDynamicSharedMemorySize, SMEM_TOTAL);

    k_prep<<<TRN_BLOCKS + GATE_BLOCKS, 256>>>(W1, x, wg);
    k_repack<<<dim3(BTOK / 16, NEXP), 256>>>();
    k_expert<<<dim3(HTILES, MTILES, NEXP), NTHR, SMEM_TOTAL>>>(W2, b1);
    k_combine<<<BTOK / 64, 64>>>(out, b2);
}

// round 15
// speedup vs baseline: 1.0318x; 1.0318x over previous
#include <cuda_runtime.h>
#include <cuda_fp16.h>
#include <cstdint>
#include <cstddef>
#include <math.h>

// ---------------- problem constants ----------------
#define BTOK  16384
#define IND   512
#define HIDD  2048
#define NEXP  8
#define NTOP  4

// ---------------- tiling ----------------
#define TM      128               // tokens per block
#define TN      128               // hidden cols per block
#define KBPST   4                 // K=16 blocks per stage => K=64
#define NST     3
#define NKCH    8                 // mainloop iterations (512/64)
#define HTILES  (HIDD / TN)       // 16
#define MTILES  (BTOK / TM)       // 128 (worst case)
#define NTHR    256

// packed-fragment stage sizes (fp16)
#define A_BYTES 16384
#define B_BYTES 16384
#define STAGE_BYTES (A_BYTES + B_BYTES)       // 32768
#define SMEM_TOTAL  (NST * STAGE_BYTES)       // 98304  (2 CTAs/SM)

#define A_TILE_BYTES  16384    // one 16-row m-tile: 32 kb x 32 lanes x 16B
#define B_TILE_BYTES  8192     // one 8-col h-tile: 32 kb x 32 lanes x 8B

// k_prep roles
#define TRN_BLOCKS 4096        // 16 hc x 32 kb x 8 e
#define GATE_BLOCKS (BTOK / 8) // 2048

// ---------------- device scratch ----------------
// A packed (half2 as uint): [e][slot/16][kb][lane][4]
//   word w: row = grp + 8*(w&1); k = kb*16 + 8*(w>>1) + 2*qid + {0,1}
__device__ __align__(1024) uint32_t g_xcu[(size_t)NEXP * BTOK * IND / 2];
// B packed (half2 as uint): [e][h/8][kb][lane][2]  (word rj: k = kb*16 + rj*8 + qid*2)
__device__ __align__(1024) uint32_t g_w1u[(size_t)NEXP * HIDD * IND / 2];
__device__ int   g_cnt[NEXP];       // zero-init; re-zeroed by k_combine each call
__device__ int   g_sel[BTOK * NTOP];
__device__ int   g_slot[BTOK * NTOP];
__device__ float g_g4[BTOK * NTOP];
__device__ float g_part[(size_t)NEXP * BTOK * HTILES];

// ---------------- helpers ----------------
__device__ __forceinline__ void cp_async16(uint32_t saddr, const void* gaddr) {
    asm volatile("cp.async.cg.shared.global [%0], [%1], 16;" :: "r"(saddr), "l"(gaddr) : "memory");
}
__device__ __forceinline__ uint32_t smem_u32(const void* p) {
    uint32_t a;
    asm("{ .reg .u64 t; cvta.to.shared.u64 t, %1; cvt.u32.u64 %0, t; }" : "=r"(a) : "l"(p));
    return a;
}
__device__ __forceinline__ void mma_f16(float* c, const uint32_t* a, const uint32_t* b) {
    asm volatile(
        "mma.sync.aligned.m16n8k16.row.col.f32.f16.f16.f32 "
        "{%0,%1,%2,%3}, {%4,%5,%6,%7}, {%8,%9}, {%0,%1,%2,%3};"
        : "+f"(c[0]), "+f"(c[1]), "+f"(c[2]), "+f"(c[3])
        : "r"(a[0]), "r"(a[1]), "r"(a[2]), "r"(a[3]), "r"(b[0]), "r"(b[1]));
}

// ============================================================
// kernel 1 (fused): blocks [0,4096) transpose W1; rest do gating
// ============================================================
__global__ void k_prep(const float* __restrict__ W1,
                       const float* __restrict__ x,
                       const float* __restrict__ wg) {
    __shared__ float tile[16][129];          // transpose role
    __shared__ int   s_cnt[NEXP];            // gate role
    __shared__ int   s_base[NEXP];

    const int tid = threadIdx.x;

    if (blockIdx.x < TRN_BLOCKS) {
        // ------- transpose role: W1 -> packed fp16 B-fragment layout -------
        int hc = blockIdx.x & 15;            // 128-h chunk
        int kb = (blockIdx.x >> 4) & 31;     // K=16 block
        int e  = blockIdx.x >> 9;

        #pragma unroll
        for (int it = 0; it < 8; ++it) {
            int idx = tid + it * 256;
            int kr = idx >> 7, hf = idx & 127;
            tile[kr][hf] = W1[((size_t)e * IND + kb * 16 + kr) * HIDD + hc * 128 + hf];
        }
        __syncthreads();

        size_t base2 = (size_t)e * (HIDD * IND / 2);
        #pragma unroll
        for (int it = 0; it < 4; ++it) {
            int w    = tid + it * 256;
            int h8l  = w >> 6;
            int rem  = w & 63;
            int lane = rem >> 1, rj = rem & 1;
            int grp  = lane >> 2, qid = lane & 3;
            int hl   = h8l * 8 + grp;
            int k0   = rj * 8 + qid * 2;
            __half2 v = __floats2half2_rn(tile[k0][hl], tile[k0 + 1][hl]);
            g_w1u[base2 + (size_t)(hc * 16 + h8l) * 2048 + (kb * 32 + lane) * 2 + rj]
                = *(uint32_t*)&v;
        }
        return;
    }

    // ------- gate role: 8 tokens per block, batched atomics -------
    int wid  = tid >> 5;
    int lane = tid & 31;
    int tok  = (blockIdx.x - TRN_BLOCKS) * 8 + wid;
    const float* xr = x + (size_t)tok * IND;

    if (tid < NEXP) s_cnt[tid] = 0;

    float acc[NEXP];
    #pragma unroll
    for (int e = 0; e < NEXP; ++e) acc[e] = 0.f;
    for (int i = lane; i < IND; i += 32) {
        float xv = xr[i];
        #pragma unroll
        for (int e = 0; e < NEXP; ++e) acc[e] = fmaf(xv, wg[i * NEXP + e], acc[e]);
    }
    #pragma unroll
    for (int off = 16; off > 0; off >>= 1) {
        #pragma unroll
        for (int e = 0; e < NEXP; ++e)
            acc[e] += __shfl_xor_sync(0xFFFFFFFFu, acc[e], off);
    }

    // top-4: strict '>' keeps lowest index on ties (matches jax.lax.top_k)
    int   sel[NTOP];
    float val[NTOP];
    bool  used[NEXP];
    #pragma unroll
    for (int e = 0; e < NEXP; ++e) used[e] = false;
    #pragma unroll
    for (int k = 0; k < NTOP; ++k) {
        float best = -1e30f; int be = 0;
        #pragma unroll
        for (int e = 0; e < NEXP; ++e)
            if (!used[e] && acc[e] > best) { best = acc[e]; be = e; }
        used[be] = true; sel[k] = be; val[k] = best;
    }
    float s = 0.f, gt[NTOP];
    #pragma unroll
    for (int k = 0; k < NTOP; ++k) { gt[k] = expf(val[k] - val[0]); s += gt[k]; }
    float inv = 1.f / s;
    #pragma unroll
    for (int k = 0; k < NTOP; ++k) gt[k] *= inv;

    // batched slot assignment: smem-local offsets, then <=8 global atomics
    __syncthreads();
    int loc[NTOP];
    if (lane == 0) {
        #pragma unroll
        for (int k = 0; k < NTOP; ++k) loc[k] = atomicAdd(&s_cnt[sel[k]], 1);
    }
    __syncthreads();
    if (tid < NEXP && s_cnt[tid] > 0) s_base[tid] = atomicAdd(&g_cnt[tid], s_cnt[tid]);
    __syncthreads();

    int slot[NTOP];
    #pragma unroll
    for (int k = 0; k < NTOP; ++k) {
        int l = __shfl_sync(0xFFFFFFFFu, loc[k], 0);
        slot[k] = s_base[sel[k]] + l;
    }

    if (lane < NTOP) {
        g_sel[tok * NTOP + lane]  = sel[lane];
        g_slot[tok * NTOP + lane] = slot[lane];
        g_g4[tok * NTOP + lane]   = gt[lane];
    }

    // pre-round row to half2 pairs, scatter into packed-fragment layout
    uint32_t hv[8];
    #pragma unroll
    for (int it = 0; it < 8; ++it) {
        int p = lane + it * 32;
        __half2 v = __floats2half2_rn(xr[2 * p], xr[2 * p + 1]);
        hv[it] = *(uint32_t*)&v;
    }
    #pragma unroll
    for (int kk = 0; kk < NTOP; ++kk) {
        int sl = slot[kk];
        size_t base2 = (size_t)sel[kk] * (BTOK * IND / 2) + (size_t)(sl >> 4) * 4096;
        int r = sl & 15, grp = r & 7, rowhalf = r >> 3;
        #pragma unroll
        for (int it = 0; it < 8; ++it) {
            int p     = lane + it * 32;
            int kb    = p >> 3;
            int khalf = (p & 7) >> 2;
            int qid   = p & 3;
            g_xcu[base2 + (size_t)(kb * 32 + grp * 4 + qid) * 4 + rowhalf + 2 * khalf]
                = hv[it];
        }
    }
}

// ============================================================
// kernel 2: expert GEMM fp16 m16n8k16 (fc1 + relu + fc2-partial)
// grid (HTILES, MTILES, NEXP), 256 threads, 2 CTAs/SM
// ============================================================
__device__ __forceinline__ void load_stage(uint32_t sb, int s, int kt, int tid,
                                           const char* Ag, const char* Bg) {
    uint32_t abase = sb + (uint32_t)s * STAGE_BYTES;
    uint32_t bbase = abase + A_BYTES;
    #pragma unroll
    for (int it = 0; it < 4; ++it) {
        int c    = tid + it * NTHR;
        int tile = c >> 7, rem = c & 127;
        cp_async16(abase + (uint32_t)c * 16,
                   Ag + (size_t)tile * A_TILE_BYTES + kt * 2048 + rem * 16);
    }
    #pragma unroll
    for (int it = 0; it < 4; ++it) {
        int c    = tid + it * NTHR;
        int tile = c >> 6, rem = c & 63;
        cp_async16(bbase + (uint32_t)c * 16,
                   Bg + (size_t)tile * B_TILE_BYTES + kt * 1024 + rem * 16);
    }
    asm volatile("cp.async.commit_group;" ::: "memory");
}

__global__ void __launch_bounds__(NTHR, 2)
k_expert(const float* __restrict__ W2, const float* __restrict__ b1) {
    extern __shared__ char smem[];
    const int e     = blockIdx.z;
    const int mtile = blockIdx.y;
    const int ht    = blockIdx.x;
    const int cnt   = g_cnt[e];
    const int m0    = mtile * TM;
    if (m0 >= cnt) return;

    const int tid  = threadIdx.x;
    const int wid  = tid >> 5;
    const int lane = tid & 31;
    const int wm   = wid >> 2;       // 0..1 : rows wm*64
    const int wn   = wid & 3;        // 0..3 : cols wn*32
    const int grp  = lane >> 2;
    const int qid  = lane & 3;

    // epilogue weight prefetch (hides gmem latency behind the mainloop)
    float w2r = 0.f, b1r = 0.f;
    if (tid < TN) {
        w2r = W2[(size_t)e * HIDD + ht * TN + tid];
        b1r = b1[(size_t)e * HIDD + ht * TN + tid];
    }

    uint32_t sb = smem_u32(smem);
    const char* Ag = (const char*)g_xcu + (size_t)e * (BTOK * IND * 2)
                   + (size_t)(m0 >> 4) * A_TILE_BYTES;
    const char* Bg = (const char*)g_w1u + (size_t)e * (HIDD * IND * 2)
                   + (size_t)(ht * (TN / 8)) * B_TILE_BYTES;

    float acc[4][4][4];
    #pragma unroll
    for (int mt = 0; mt < 4; ++mt)
        #pragma unroll
        for (int nt = 0; nt < 4; ++nt)
            #pragma unroll
            for (int r = 0; r < 4; ++r) acc[mt][nt][r] = 0.f;

    load_stage(sb, 0, 0, tid, Ag, Bg);
    load_stage(sb, 1, 1, tid, Ag, Bg);

    for (int kt = 0; kt < NKCH; ++kt) {
        asm volatile("cp.async.wait_group 1;" ::: "memory");
        __syncthreads();
        int kn = kt + 2;
        if (kn < NKCH) load_stage(sb, kn % NST, kn, tid, Ag, Bg);
        else asm volatile("cp.async.commit_group;" ::: "memory");

        int cs = kt % NST;
        const uint4* sA = (const uint4*)(smem + (size_t)cs * STAGE_BYTES);
        const uint2* sB = (const uint2*)(smem + (size_t)cs * STAGE_BYTES + A_BYTES);

        #pragma unroll
        for (int ks = 0; ks < KBPST; ++ks) {             // 4 K=16 steps
            uint4 af[4];
            uint2 bf[4];
            #pragma unroll
            for (int mt = 0; mt < 4; ++mt)
                af[mt] = sA[((wm * 4 + mt) * 4 + ks) * 32 + lane];
            #pragma unroll
            for (int nt = 0; nt < 4; ++nt)
                bf[nt] = sB[((wn * 4 + nt) * 4 + ks) * 32 + lane];
            #pragma unroll
            for (int mt = 0; mt < 4; ++mt)
                #pragma unroll
                for (int nt = 0; nt < 4; ++nt)
                    mma_f16(acc[mt][nt], (const uint32_t*)&af[mt], (const uint32_t*)&bf[nt]);
        }
    }
    __syncthreads();

    // ---- fused epilogue: relu(h + b1) . W2 over this 128-col tile ----
    float* red = (float*)smem;                 // [TM][4]
    float* w2s = (float*)(smem + TM * 4 * 4);  // [TN]
    float* b1s = w2s + TN;                     // [TN]
    if (tid < TN) {
        w2s[tid] = w2r;
        b1s[tid] = b1r;
    }
    __syncthreads();

    #pragma unroll
    for (int mt = 0; mt < 4; ++mt) {
        #pragma unroll
        for (int rr = 0; rr < 2; ++rr) {
            int row = wm * 64 + mt * 16 + grp + rr * 8;
            float v = 0.f;
            #pragma unroll
            for (int nt = 0; nt < 4; ++nt) {
                int col = wn * 32 + nt * 8 + qid * 2;
                float h0 = fmaxf(acc[mt][nt][rr * 2 + 0] + b1s[col], 0.f);
                float h1 = fmaxf(acc[mt][nt][rr * 2 + 1] + b1s[col + 1], 0.f);
                v = fmaf(h0, w2s[col], v);
                v = fmaf(h1, w2s[col + 1], v);
            }
            v += __shfl_down_sync(0xFFFFFFFFu, v, 2);
            v += __shfl_down_sync(0xFFFFFFFFu, v, 1);
            if (qid == 0) red[row * 4 + wn] = v;
        }
    }
    __syncthreads();

    if (tid < TM) {
        float p = red[tid * 4 + 0] + red[tid * 4 + 1] + red[tid * 4 + 2] + red[tid * 4 + 3];
        g_part[((size_t)e * BTOK + m0 + tid) * HTILES + ht] = p;
    }
}

// ============================================================
// kernel 3: weighted combine + counter reset for next call
// ============================================================
__global__ void k_combine(float* __restrict__ out, const float* __restrict__ b2) {
    int t = blockIdx.x * blockDim.x + threadIdx.x;
    if (blockIdx.x == 0 && threadIdx.x < NEXP) g_cnt[threadIdx.x] = 0;
    if (t >= BTOK) return;
    float y = 0.f;
    #pragma unroll
    for (int k = 0; k < NTOP; ++k) {
        int   e = g_sel[t * NTOP + k];
        int   s = g_slot[t * NTOP + k];
        float g = g_g4[t * NTOP + k];
        float p = b2[e];
        const float* pp = &g_part[((size_t)e * BTOK + s) * HTILES];
        #pragma unroll
        for (int h = 0; h < HTILES; ++h) p += pp[h];
        y = fmaf(g, p, y);
    }
    out[t] = y;
}

// ============================================================
// launch
// ============================================================
extern "C" void kernel_launch(void* const* d_in, const int* in_sizes, int n_in,
                              void* d_out, int out_size) {
    const float* x  = (const float*)d_in[0];   // [16384, 512]
    const float* wg = (const float*)d_in[1];   // [512, 8]
    const float* W1 = (const float*)d_in[2];   // [8, 512, 2048]
    const float* b1 = (const float*)d_in[3];   // [8, 2048]
    const float* W2 = (const float*)d_in[4];   // [8, 2048, 1]
    const float* b2 = (const float*)d_in[5];   // [8, 1]
    float* out = (float*)d_out;                // [16384, 1]

    cudaFuncSetAttribute(k_expert, cudaFuncAttributeMaxDynamicSharedMemorySize, SMEM_TOTAL);

    k_prep<<<TRN_BLOCKS + GATE_BLOCKS, 256>>>(W1, x, wg);
    k_expert<<<dim3(HTILES, MTILES, NEXP), NTHR, SMEM_TOTAL>>>(W2, b1);
    k_combine<<<BTOK / 64, 64>>>(out, b2);
}